// round 16
// baseline (speedup 1.0000x reference)
#include <cuda_runtime.h>

// quadLayer: out[b,h,w, c*512 + a*32 + f] =
//   sum_m p[a][m] W1[c][m][f] + sum_{m1,m2} p[a][m1] p[a][m2] W2[c][m1*4+m2][f]
// p[a][mm] = x[b, 2h+((a>>2)>>1), 2w+((a>>2)&1), 4*(a&3)+mm]  (one float4 of x).
//
// R16: Horner symmetric quadratic with f-QUAD output packing. Thread =
// (pixpar, c, fq) owns one c-plane and f = 4fq..4fq+3 as two f32x2 half-
// lattices (serialized, register-isomorphic to R13's two planes). Per
// (pix, a): 2 LDS.128 of duplicated {p,p} pairs, 30 FFMA2, ONE st.global
// .cs.v4 (12 LSU-cyc) instead of 4 STG.32 (20) — attacks the LSU-dispatch
// serializer that pinned issue at 44% for six rounds.

#define NPIX 4
#define THREADS 256

__device__ __forceinline__ unsigned long long pack2(float lo, float hi) {
    unsigned long long r;
    asm("mov.b64 %0, {%1,%2};" : "=l"(r) : "f"(lo), "f"(hi));
    return r;
}

__device__ __forceinline__ void fma2(unsigned long long &d,
                                     unsigned long long a,
                                     unsigned long long b) {
    asm("fma.rn.f32x2 %0, %1, %2, %0;" : "+l"(d) : "l"(a), "l"(b));
}

__device__ __forceinline__ unsigned long long fma2n(unsigned long long a,
                                                    unsigned long long b,
                                                    unsigned long long c) {
    unsigned long long d;
    asm("fma.rn.f32x2 %0, %1, %2, %3;" : "=l"(d) : "l"(a), "l"(b), "l"(c));
    return d;
}

__device__ __forceinline__ unsigned long long mul2(unsigned long long a,
                                                   unsigned long long b) {
    unsigned long long d;
    asm("mul.rn.f32x2 %0, %1, %2;" : "=l"(d) : "l"(a), "l"(b));
    return d;
}

__device__ __forceinline__ unsigned long long add2(unsigned long long a,
                                                   unsigned long long b) {
    unsigned long long r;
    asm("add.rn.f32x2 %0, %1, %2;" : "=l"(r) : "l"(a), "l"(b));
    return r;
}

// one f-pair half-lattice of the Horner quadratic
__device__ __forceinline__ unsigned long long plane_eval(
    unsigned long long pp0, unsigned long long pp1,
    unsigned long long pp2, unsigned long long pp3,
    const unsigned long long* __restrict__ lin,
    const unsigned long long* __restrict__ q)
{
    // q idx: (0,0)=0 (0,1)=1 (0,2)=2 (0,3)=3 (1,1)=4 (1,2)=5 (1,3)=6
    //        (2,2)=7 (2,3)=8 (3,3)=9
    unsigned long long t0 = fma2n(pp0, q[0], lin[0]);
    unsigned long long t1 = fma2n(pp1, q[4], lin[1]);
    unsigned long long t2 = fma2n(pp2, q[7], lin[2]);
    unsigned long long t3 = fma2n(pp3, q[9], lin[3]);
    fma2(t0, pp1, q[1]);
    fma2(t1, pp2, q[5]);
    fma2(t2, pp3, q[8]);
    fma2(t0, pp2, q[2]);
    fma2(t1, pp3, q[6]);
    fma2(t0, pp3, q[3]);
    unsigned long long s0 = mul2(pp0, t0);
    unsigned long long s1 = mul2(pp1, t1);
    fma2(s0, pp2, t2);
    fma2(s1, pp3, t3);
    return add2(s0, s1);
}

__global__ void __launch_bounds__(THREADS, 3)
quad_kernel(const float* __restrict__ x,
            const float* __restrict__ W1,
            const float* __restrict__ W2,
            float* __restrict__ out)
{
    // duplicated base values: NPIX * 16 a * 4 m * 2 dup floats = 2 KB
    __shared__ __align__(16) float pb[NPIX * 16 * 8];

    const int t      = threadIdx.x;
    const int pixpar = t >> 7;        // 0..1
    const int c      = (t >> 3) & 15; // 0..15
    const int fq     = t & 7;         // 0..7 -> f = 4fq..4fq+3
    const int f0     = 4 * fq;

    // ---- weights, f-pair packed: lin0/q0 = {f0,f0+1}, lin1/q1 = {f0+2,f0+3} ----
    unsigned long long lin0[4], lin1[4], q0[10], q1[10];
    {
        const float* w1c = W1 + c * 128 + f0;
        const float* w2c = W2 + c * 512 + f0;
#pragma unroll
        for (int m = 0; m < 4; m++) {
            lin0[m] = pack2(w1c[m * 32],     w1c[m * 32 + 1]);
            lin1[m] = pack2(w1c[m * 32 + 2], w1c[m * 32 + 3]);
        }
        int k = 0;
#pragma unroll
        for (int m1 = 0; m1 < 4; m1++)
#pragma unroll
            for (int m2 = m1; m2 < 4; m2++) {
                float a0, a1, a2, a3;
                if (m1 == m2) {
                    const int d = (5 * m1) * 32;
                    a0 = w2c[d];     a1 = w2c[d + 1];
                    a2 = w2c[d + 2]; a3 = w2c[d + 3];
                } else {
                    const int qa = (m1 * 4 + m2) * 32, qb = (m2 * 4 + m1) * 32;
                    a0 = w2c[qa]     + w2c[qb];
                    a1 = w2c[qa + 1] + w2c[qb + 1];
                    a2 = w2c[qa + 2] + w2c[qb + 2];
                    a3 = w2c[qa + 3] + w2c[qb + 3];
                }
                q0[k] = pack2(a0, a1);
                q1[k] = pack2(a2, a3);
                k++;
            }
    }

    // ---- base-value build: one thread per (pix, a), values duplicated ----
    if (t < NPIX * 16) {
        const int pix = t >> 4;
        const int a   = t & 15;
        const int g   = blockIdx.x * NPIX + pix;   // global pixel id
        const int b   = g >> 10;
        const int h   = (g >> 5) & 31;
        const int wc  = g & 31;
        const int m   = a >> 2;
        const int i   = m >> 1;
        const int j   = m & 1;
        const int ch0 = (a & 3) * 4;
        const float4 v = *reinterpret_cast<const float4*>(
            x + (((b * 64 + 2 * h + i) * 64) + (2 * wc + j)) * 16 + ch0);
        float* fb = &pb[(pix * 16 + a) * 8];
        fb[0] = v.x; fb[1] = v.x;
        fb[2] = v.y; fb[3] = v.y;
        fb[4] = v.z; fb[5] = v.z;
        fb[6] = v.w; fb[7] = v.w;
    }
    __syncthreads();

    const unsigned int sbase = (unsigned int)__cvta_generic_to_shared(pb);
    const size_t gbase = (size_t)blockIdx.x * NPIX * 8192 + (size_t)(c * 512 + f0);

#pragma unroll 1
    for (int pp = 0; pp < NPIX / 2; pp++) {
        const int pix = 2 * pp + pixpar;
        float* op = out + gbase + (size_t)pix * 8192;
        unsigned int saddr = sbase + pix * 512;   // 16 a * 32 B

#pragma unroll
        for (int a = 0; a < 16; a++) {
            unsigned long long pp0, pp1, pp2, pp3;
            asm("ld.shared.v2.u64 {%0,%1}, [%2];"
                : "=l"(pp0), "=l"(pp1) : "r"(saddr));
            asm("ld.shared.v2.u64 {%0,%1}, [%2];"
                : "=l"(pp2), "=l"(pp3) : "r"(saddr + 16));
            saddr += 32;

            const unsigned long long s0 = plane_eval(pp0, pp1, pp2, pp3, lin0, q0);
            const unsigned long long s1 = plane_eval(pp0, pp1, pp2, pp3, lin1, q1);

            float r0, r1, r2, r3;
            asm("mov.b64 {%0,%1}, %2;" : "=f"(r0), "=f"(r1) : "l"(s0));
            asm("mov.b64 {%0,%1}, %2;" : "=f"(r2), "=f"(r3) : "l"(s1));
            asm("st.global.cs.v4.f32 [%0], {%1,%2,%3,%4};"
                :: "l"(op + a * 32), "f"(r0), "f"(r1), "f"(r2), "f"(r3)
                : "memory");
        }
    }
}

extern "C" void kernel_launch(void* const* d_in, const int* in_sizes, int n_in,
                              void* d_out, int out_size) {
    const float* x  = (const float*)d_in[0];
    const float* W1 = (const float*)d_in[1];
    const float* W2 = (const float*)d_in[2];
    float* out = (float*)d_out;
    quad_kernel<<<8192 / NPIX, THREADS>>>(x, W1, W2, out);
}

// round 17
// speedup vs baseline: 1.2335x; 1.2335x over previous
#include <cuda_runtime.h>

// quadLayer: out[b,h,w, c*512 + a*32 + f] =
//   sum_m p[a][m] W1[c][m][f] + sum_{m1,m2} p[a][m1] p[a][m2] W2[c][m1*4+m2][f]
// p[a][mm] = x[b, 2h+((a>>2)>>1), 2w+((a>>2)&1), 4*(a&3)+mm]  (one float4 of x).
//
// R17 = R13 (champion: Horner symmetric quadratic, a-parity-packed smem,
// NPIX=4, 3 CTAs/SM, 1-deep LDS prefetch, serialized planes) with ONE change:
// stores use default cache policy instead of .cs. Warps appear blocked on the
// store/L2-write drain path; .cs (evict-first) may be throttling it.

#define NPIX 4
#define THREADS 256

__device__ __forceinline__ unsigned long long pack2(float lo, float hi) {
    unsigned long long r;
    asm("mov.b64 %0, {%1,%2};" : "=l"(r) : "f"(lo), "f"(hi));
    return r;
}

__device__ __forceinline__ void fma2(unsigned long long &d,
                                     unsigned long long a,
                                     unsigned long long b) {
    asm("fma.rn.f32x2 %0, %1, %2, %0;" : "+l"(d) : "l"(a), "l"(b));
}

__device__ __forceinline__ unsigned long long fma2n(unsigned long long a,
                                                    unsigned long long b,
                                                    unsigned long long c) {
    unsigned long long d;
    asm("fma.rn.f32x2 %0, %1, %2, %3;" : "=l"(d) : "l"(a), "l"(b), "l"(c));
    return d;
}

__device__ __forceinline__ unsigned long long mul2(unsigned long long a,
                                                   unsigned long long b) {
    unsigned long long d;
    asm("mul.rn.f32x2 %0, %1, %2;" : "=l"(d) : "l"(a), "l"(b));
    return d;
}

__device__ __forceinline__ unsigned long long add2(unsigned long long a,
                                                   unsigned long long b) {
    unsigned long long r;
    asm("add.rn.f32x2 %0, %1, %2;" : "=l"(r) : "l"(a), "l"(b));
    return r;
}

__device__ __forceinline__ void store2(float* p, unsigned long long s) {
    float lo, hi;
    asm("mov.b64 {%0,%1}, %2;" : "=f"(lo), "=f"(hi) : "l"(s));
    asm("st.global.f32 [%0], %1;" :: "l"(p),      "f"(lo) : "memory");
    asm("st.global.f32 [%0], %1;" :: "l"(p + 32), "f"(hi) : "memory");
}

// one plane of the Horner lattice; tight register lifetime
__device__ __forceinline__ unsigned long long plane_eval(
    unsigned long long pp0, unsigned long long pp1,
    unsigned long long pp2, unsigned long long pp3,
    const unsigned long long* __restrict__ lin,
    const unsigned long long* __restrict__ q)
{
    // q idx: (0,0)=0 (0,1)=1 (0,2)=2 (0,3)=3 (1,1)=4 (1,2)=5 (1,3)=6
    //        (2,2)=7 (2,3)=8 (3,3)=9
    unsigned long long t0 = fma2n(pp0, q[0], lin[0]);
    unsigned long long t1 = fma2n(pp1, q[4], lin[1]);
    unsigned long long t2 = fma2n(pp2, q[7], lin[2]);
    unsigned long long t3 = fma2n(pp3, q[9], lin[3]);
    fma2(t0, pp1, q[1]);
    fma2(t1, pp2, q[5]);
    fma2(t2, pp3, q[8]);
    fma2(t0, pp2, q[2]);
    fma2(t1, pp3, q[6]);
    fma2(t0, pp3, q[3]);
    unsigned long long s0 = mul2(pp0, t0);
    unsigned long long s1 = mul2(pp1, t1);
    fma2(s0, pp2, t2);
    fma2(s1, pp3, t3);
    return add2(s0, s1);
}

__global__ void __launch_bounds__(THREADS, 3)
quad_kernel(const float* __restrict__ x,
            const float* __restrict__ W1,
            const float* __restrict__ W2,
            float* __restrict__ out)
{
    // base values (NPIX*8 ap * 4 m * 2 parity floats = 1 KB) + 32B pad for
    // the final over-prefetch.
    __shared__ __align__(16) float pbase[NPIX * 8 * 4 * 2 + 8];

    const int t  = threadIdx.x;
    const int c0 = t >> 5;   // 0..7  (planes c0 and c0+8)
    const int f  = t & 31;   // 0..31

    // ---- weights (duplicated f32x2), Horner layout ----
    unsigned long long linA[4], linB[4], qA[10], qB[10];
    {
        const float* w1a = W1 + c0 * 128 + f;
        const float* w1b = W1 + (c0 + 8) * 128 + f;
        const float* w2a = W2 + c0 * 512 + f;
        const float* w2b = W2 + (c0 + 8) * 512 + f;
#pragma unroll
        for (int m = 0; m < 4; m++) {
            float a = w1a[m * 32], b = w1b[m * 32];
            linA[m] = pack2(a, a);
            linB[m] = pack2(b, b);
        }
        int k = 0;
#pragma unroll
        for (int m1 = 0; m1 < 4; m1++)
#pragma unroll
            for (int m2 = m1; m2 < 4; m2++) {
                float a, b;
                if (m1 == m2) {
                    a = w2a[(5 * m1) * 32];
                    b = w2b[(5 * m1) * 32];
                } else {
                    a = w2a[(m1 * 4 + m2) * 32] + w2a[(m2 * 4 + m1) * 32];
                    b = w2b[(m1 * 4 + m2) * 32] + w2b[(m2 * 4 + m1) * 32];
                }
                qA[k] = pack2(a, a);
                qB[k] = pack2(b, b);
                k++;
            }
    }

    // ---- base-value build: one thread per (pix, a); NPIX*16 = 64 threads ----
    if (t < NPIX * 16) {
        const int pix = t >> 4;
        const int a   = t & 15;
        const int g   = blockIdx.x * NPIX + pix;   // global pixel id
        const int b   = g >> 10;
        const int h   = (g >> 5) & 31;
        const int wc  = g & 31;
        const int m   = a >> 2;
        const int i   = m >> 1;
        const int j   = m & 1;
        const int ch0 = (a & 3) * 4;
        const float4 v = *reinterpret_cast<const float4*>(
            x + (((b * 64 + 2 * h + i) * 64) + (2 * wc + j)) * 16 + ch0);
        float* fb = &pbase[(pix * 8 + (a >> 1)) * 8 + (a & 1)];
        fb[0] = v.x; fb[2] = v.y; fb[4] = v.z; fb[6] = v.w;
    }
    __syncthreads();

    // incremental output pointers for the two planes
    float* outA = out + (size_t)blockIdx.x * NPIX * 8192 + (size_t)(c0 * 512 + f);
    float* outB = outA + 8 * 512;
    unsigned int saddr = (unsigned int)__cvta_generic_to_shared(pbase);

    // ---- software-pipelined main loop: prefetch depth 1 ----
    unsigned long long p0, p1, p2, p3;   // current operands
    asm("ld.shared.v2.u64 {%0,%1}, [%2];" : "=l"(p0), "=l"(p1) : "r"(saddr));
    asm("ld.shared.v2.u64 {%0,%1}, [%2];" : "=l"(p2), "=l"(p3) : "r"(saddr + 16));
    saddr += 32;

#pragma unroll 1
    for (int pix = 0; pix < NPIX; pix++) {
#pragma unroll
        for (int ap = 0; ap < 8; ap++) {
            // prefetch next iteration's operands (pad covers the last one)
            unsigned long long n0, n1, n2, n3;
            asm("ld.shared.v2.u64 {%0,%1}, [%2];"
                : "=l"(n0), "=l"(n1) : "r"(saddr));
            asm("ld.shared.v2.u64 {%0,%1}, [%2];"
                : "=l"(n2), "=l"(n3) : "r"(saddr + 16));
            saddr += 32;

            // plane A, then plane B (serialized to bound live registers)
            store2(outA + (2 * ap) * 32, plane_eval(p0, p1, p2, p3, linA, qA));
            store2(outB + (2 * ap) * 32, plane_eval(p0, p1, p2, p3, linB, qB));

            p0 = n0; p1 = n1; p2 = n2; p3 = n3;   // rotated away by unroll
        }
        outA += 8192;
        outB += 8192;
    }
}

extern "C" void kernel_launch(void* const* d_in, const int* in_sizes, int n_in,
                              void* d_out, int out_size) {
    const float* x  = (const float*)d_in[0];
    const float* W1 = (const float*)d_in[1];
    const float* W2 = (const float*)d_in[2];
    float* out = (float*)d_out;
    quad_kernel<<<8192 / NPIX, THREADS>>>(x, W1, W2, out);
}